// round 15
// baseline (speedup 1.0000x reference)
#include <cuda_runtime.h>
#include <cuda_fp16.h>
#include <stdint.h>

// Problem constants
#define NREAL 8100   // 90*90 valid patches per image
#define NPAD  8192   // padded patch count
#define DREAL 147    // 3*7*7
#define KSG   160    // K storage per patch row in global (bf16 elems; 320 B)
#define NIMG  4
#define ALPHA_F 0.05f
#define JCHUNK 64
#define TOTAL_ITEMS (NIMG * 64 * 128)   // (b, i-block, j-chunk) tuples = 32768
#define NWORKERS 296                    // 148 SMs x 2 CTAs

// -------- device scratch ----------------------------------------------------
// k storage is PAIR-PERMUTED within each 16-block (see k_prep); applied to
// BOTH X and Y so dot products and norms are unchanged.
__device__ uint16_t g_XP[NIMG * NPAD * KSG];   // bf16 bits
__device__ uint16_t g_YP[NIMG * NPAD * KSG];
__device__ float g_X2[NIMG * NPAD];
__device__ float g_Y2[NIMG * NPAD];
__device__ unsigned int g_RM[NIMG * NPAD];     // row mins (float bits)
__device__ unsigned int g_CM[NIMG * NPAD];     // col mins (float bits)
__device__ __half g_DH[(size_t)NIMG * NPAD * NPAD];  // [b][j][i] fp16 dist

__device__ __forceinline__ float finf() { return __int_as_float(0x7f800000); }

__device__ __forceinline__ uint16_t to_bf16(float v) {
    uint16_t u;
    asm("cvt.rn.bf16.f32 %0, %1;" : "=h"(u) : "f"(v));
    return u;
}

// bf16 warp MMA, K=16 (sm_80+; legal on plain sm_100 target)
#define MMA16(c0,c1,c2,c3,a0,a1,a2,a3,b0,b1) \
    asm volatile("mma.sync.aligned.m16n8k16.row.col.f32.bf16.bf16.f32 " \
        "{%0,%1,%2,%3}, {%4,%5,%6,%7}, {%8,%9}, {%0,%1,%2,%3};" \
        : "+f"(c0), "+f"(c1), "+f"(c2), "+f"(c3) \
        : "r"(a0), "r"(a1), "r"(a2), "r"(a3), "r"(b0), "r"(b1))

// SMEM (bytes): X 128x352 | Y 2 stages x 64x352 | fp16 staging 64x272 | RMS
#define SMB_X   0
#define SMB_Y   45056
#define SMB_ST  (45056 + 45056)
#define SMB_RMS (SMB_ST + 64 * 272)
#define SM_TOTAL (SMB_RMS + 1024)    // 108544 B -> 2 CTAs/SM

// -------- fused prep: extract bf16 (pair-permuted) + norms + min-init -------
__global__ void k_prep(const float* __restrict__ xsrc, const float* __restrict__ ysrc) {
    int row  = blockIdx.x * 8 + (threadIdx.x >> 5);
    int lane = threadIdx.x & 31;
    int b = row >> 13, n = row & (NPAD - 1);
    if (lane == 0) { g_RM[row] = 0x7f800000u; g_CM[row] = 0x7f800000u; }

    float sx = 0.0f, sy = 0.0f;
    if (lane < 20) {
        uint32_t px[4], py[4];
        const bool valid = (n < NREAL);
        const int oy = n / 90, ox = n - (n / 90) * 90;
        const float* xb = xsrc + b * 3 * 96 * 96;
        const float* yb = ysrc + b * 3 * 96 * 96;
#pragma unroll
        for (int e = 0; e < 8; e++) {
            int kq = lane * 8 + e;
            int s = kq & 15, p = s >> 1;
            int k = (kq & ~15) + (p & 1) * 8 + (p >> 1) * 2 + (s & 1);  // logical k
            uint32_t vx = 0, vy = 0;
            if (valid && k < DREAL) {
                int c = k / 49, rr = (k % 49) / 7, ss = k % 7;
                int off = ((c * 96) + oy + rr) * 96 + ox + ss;
                vx = to_bf16(xb[off]);
                vy = to_bf16(yb[off]);
                float fx = __uint_as_float(vx << 16); sx += fx * fx;
                float fy = __uint_as_float(vy << 16); sy += fy * fy;
            }
            if (e & 1) { px[e >> 1] |= vx << 16; py[e >> 1] |= vy << 16; }
            else       { px[e >> 1]  = vx;       py[e >> 1]  = vy; }
        }
        *(uint4*)((char*)g_XP + (size_t)row * 320 + lane * 16) =
            make_uint4(px[0], px[1], px[2], px[3]);
        *(uint4*)((char*)g_YP + (size_t)row * 320 + lane * 16) =
            make_uint4(py[0], py[1], py[2], py[3]);
    }
#pragma unroll
    for (int off = 16; off > 0; off >>= 1) {
        sx += __shfl_xor_sync(0xffffffffu, sx, off);
        sy += __shfl_xor_sync(0xffffffffu, sy, off);
    }
    if (lane == 0) { g_X2[row] = sx; g_Y2[row] = sy; }
}

// -------- pass 0: persistent balanced bf16 GEMM + row-min + fp16 dist -------
// Grid: exactly NWORKERS CTAs; CTA w owns items [w*T/296, (w+1)*T/296).
__global__ void __launch_bounds__(256, 2) k_pass0() {
    extern __shared__ char smem[];
    char* XS = smem + SMB_X;
    char* YS = smem + SMB_Y;
    char* ST = smem + SMB_ST;
    unsigned int* RMS = (unsigned int*)(smem + SMB_RMS);

    const int w = blockIdx.x;
    const int start = (int)(((long long)TOTAL_ITEMS * w) / NWORKERS);
    const int end   = (int)(((long long)TOTAL_ITEMS * (w + 1)) / NWORKERS);

    const int tid = threadIdx.x;
    const int lane = tid & 31;
    const int g = lane >> 2, t = lane & 3;
    const int wj = (tid >> 5) >> 2;
    const int wi = (tid >> 5) & 3;

    // per-thread Y-copy slot mapping (item-invariant)
    int sofs[5], gofs[5];
#pragma unroll
    for (int s = 0; s < 5; s++) {
        int v = tid + s * 256;
        int r = v / 20, q = v - r * 20;
        sofs[s] = r * 352 + q * 16;
        gofs[s] = r * 320 + q * 16;
    }

    // initial Y load for first item
    {
        int bi = start >> 7, jt = start & 127;
        const char* src = (const char*)g_YP
            + ((size_t)(bi >> 6) * NPAD + (size_t)jt * JCHUNK) * 320;
        char* Yst = YS + (start & 1) * 22528;
#pragma unroll
        for (int s = 0; s < 5; s++)
            *(float4*)(Yst + sofs[s]) = *(const float4*)(src + gofs[s]);
    }

    int cur_bi = -1;
    int b = 0, i0 = 0;
    float x2r[4][2];                       // pre-scaled by invD (+inf invalid)
    const float invD   = 1.0f / (float)DREAL;
    const float m2invD = -2.0f * invD;

    for (int item = start; item < end; item++) {
        const int bi = item >> 7;
        const int jt = item & 127;
        if (bi != cur_bi) {                // uniform branch
            cur_bi = bi;
            b  = bi >> 6;
            i0 = (bi & 63) * 128;
            __syncthreads();               // old XS reads fenced
            const float4* G4 = (const float4*)((const char*)g_XP
                                + ((size_t)b * NPAD + i0) * 320);
            float4* X4 = (float4*)XS;
            for (int v = tid; v < 128 * 20; v += 256) {
                int r = v / 20, q = v - r * 20;
                X4[r * 22 + q] = G4[r * 20 + q];
            }
#pragma unroll
            for (int nf = 0; nf < 4; nf++)
#pragma unroll
                for (int p = 0; p < 2; p++) {
                    int i = i0 + wi * 32 + nf * 8 + t * 2 + p;
                    x2r[nf][p] = (i < NREAL) ? g_X2[b * NPAD + i] * invD : finf();
                }
            __syncthreads();               // XS (and initial Y) visible
        }

        const char* Yu = YS + (item & 1) * 22528;
        const int jbase = jt * JCHUNK;

        // prefetch this chunk's y2 (pre-scaled) — hides L2 latency under MMAs
        float y2p[2][2];
#pragma unroll
        for (int f = 0; f < 2; f++)
#pragma unroll
            for (int h = 0; h < 2; h++)
                y2p[f][h] = g_Y2[b * NPAD + jbase + wj * 32 + f * 16 + h * 8 + g] * invD;

        // prefetch next item's Y into registers
        float4 pf[5];
        const bool havepf = (item + 1 < end);
        if (havepf) {
            int bin = (item + 1) >> 7, jtn = (item + 1) & 127;
            const char* Ygn = (const char*)g_YP
                + ((size_t)(bin >> 6) * NPAD + (size_t)jtn * JCHUNK) * 320;
#pragma unroll
            for (int s = 0; s < 5; s++) pf[s] = *(const float4*)(Ygn + gofs[s]);
        }

        // ---- 64x128 chunk GEMM: warp 32j x 32i, m16n8k16 bf16, 10 K-steps ---
        float c[2][4][4];
#pragma unroll
        for (int f = 0; f < 2; f++)
#pragma unroll
            for (int nf = 0; nf < 4; nf++)
#pragma unroll
                for (int k = 0; k < 4; k++) c[f][nf][k] = 0.0f;

#pragma unroll
        for (int ks = 0; ks < 10; ks++) {
            uint32_t a[2][4], bb[4][2];
            const int ko = ks * 32 + t * 8;
#pragma unroll
            for (int f = 0; f < 2; f++) {
                int row = wj * 32 + f * 16 + g;
                uint2 lo = *(const uint2*)(Yu + row * 352 + ko);
                uint2 hi = *(const uint2*)(Yu + (row + 8) * 352 + ko);
                a[f][0] = lo.x; a[f][2] = lo.y;
                a[f][1] = hi.x; a[f][3] = hi.y;
            }
#pragma unroll
            for (int nf = 0; nf < 4; nf++) {
                int col = wi * 32 + nf * 8 + g;
                uint2 bv = *(const uint2*)(XS + col * 352 + ko);
                bb[nf][0] = bv.x; bb[nf][1] = bv.y;
            }
#pragma unroll
            for (int f = 0; f < 2; f++)
#pragma unroll
                for (int nf = 0; nf < 4; nf++)
                    MMA16(c[f][nf][0], c[f][nf][1], c[f][nf][2], c[f][nf][3],
                          a[f][0], a[f][1], a[f][2], a[f][3], bb[nf][0], bb[nf][1]);
        }

        // commit prefetched Y to the other stage
        if (havepf) {
            char* Yn = YS + ((item + 1) & 1) * 22528;
#pragma unroll
            for (int s = 0; s < 5; s++) *(float4*)(Yn + sofs[s]) = pf[s];
        }

        // ---- epilogue: dist -> fp16 staging + row-min to RMS ---------------
#pragma unroll
        for (int f = 0; f < 2; f++)
#pragma unroll
            for (int h = 0; h < 2; h++) {
                int jl = wj * 32 + f * 16 + h * 8 + g;
                float y2s = y2p[f][h];
                float rm_ = finf();
                uint32_t* srow = (uint32_t*)(ST + jl * 272 + wi * 64 + t * 4);
#pragma unroll
                for (int nf = 0; nf < 4; nf++) {
                    float d0 = fmaxf(fmaf(c[f][nf][2*h],   m2invD, y2s + x2r[nf][0]), 0.0f);
                    float d1 = fmaxf(fmaf(c[f][nf][2*h+1], m2invD, y2s + x2r[nf][1]), 0.0f);
                    __half2 hp = __floats2half2_rn(d0, d1);
                    srow[nf * 4] = *(uint32_t*)&hp;
                    rm_ = fminf(rm_, fminf(d0, d1));
                }
                rm_ = fminf(rm_, __shfl_xor_sync(0xffffffffu, rm_, 1));
                rm_ = fminf(rm_, __shfl_xor_sync(0xffffffffu, rm_, 2));
                if (t == 0) RMS[wi * 64 + jl] = __float_as_uint(rm_);
            }
        __syncthreads();

        // coalesced STG of staging (64 rows x 256B) + row-min global reduce
        {
            char* gb = (char*)g_DH + (((size_t)b * NPAD + jbase) * NPAD + i0) * 2;
#pragma unroll
            for (int s2 = 0; s2 < 4; s2++) {
                int v = tid + s2 * 256;
                int r = v >> 4, q = v & 15;
                uint4 val = *(uint4*)(ST + r * 272 + q * 16);
                *(uint4*)(gb + (size_t)r * (NPAD * 2) + q * 16) = val;
            }
        }
        if (tid < 64) {
            unsigned int m = min(min(RMS[tid], RMS[64 + tid]),
                                 min(RMS[128 + tid], RMS[192 + tid]));
            int j = jbase + tid;
            if (j < NREAL) atomicMin(&g_RM[b * NPAD + j], m);
        }
        __syncthreads();
    }
}

// -------- pass 1: streaming column-min over fp16 dist (rinv fused) ----------
#define JSPLIT 450   // 18 * 450 = 8100
__global__ void __launch_bounds__(256) k_colmin() {
    __shared__ float rs[JSPLIT];
    const int b  = blockIdx.z;
    const int j0 = blockIdx.y * JSPLIT;
    const int i  = blockIdx.x * 512 + threadIdx.x * 2;

    for (int r = threadIdx.x; r < JSPLIT; r += 256) {
        float rm = __uint_as_float(g_RM[b * NPAD + j0 + r]);   // j0+r < NREAL
        rs[r] = 1.0f / (rm + ALPHA_F);
    }
    __syncthreads();

    const __half2* dp = (const __half2*)(g_DH + ((size_t)(b * NPAD + j0)) * NPAD + i);
    float a0 = finf(), a1 = finf(), a2 = finf();
    float b0 = finf(), b1 = finf(), b2 = finf();
    for (int j = 0; j < JSPLIT; j += 6) {   // 450 = 6*75
        __half2 u0 = dp[(size_t)(j + 0) * (NPAD / 2)];
        __half2 u1 = dp[(size_t)(j + 1) * (NPAD / 2)];
        __half2 u2 = dp[(size_t)(j + 2) * (NPAD / 2)];
        __half2 u3 = dp[(size_t)(j + 3) * (NPAD / 2)];
        __half2 u4 = dp[(size_t)(j + 4) * (NPAD / 2)];
        __half2 u5 = dp[(size_t)(j + 5) * (NPAD / 2)];
        float2 f0 = __half22float2(u0), f1 = __half22float2(u1);
        float2 f2 = __half22float2(u2), f3 = __half22float2(u3);
        float2 f4 = __half22float2(u4), f5 = __half22float2(u5);
        a0 = fminf(a0, f0.x * rs[j + 0]); b0 = fminf(b0, f0.y * rs[j + 0]);
        a1 = fminf(a1, f1.x * rs[j + 1]); b1 = fminf(b1, f1.y * rs[j + 1]);
        a2 = fminf(a2, f2.x * rs[j + 2]); b2 = fminf(b2, f2.y * rs[j + 2]);
        a0 = fminf(a0, f3.x * rs[j + 3]); b0 = fminf(b0, f3.y * rs[j + 3]);
        a1 = fminf(a1, f4.x * rs[j + 4]); b1 = fminf(b1, f4.y * rs[j + 4]);
        a2 = fminf(a2, f5.x * rs[j + 5]); b2 = fminf(b2, f5.y * rs[j + 5]);
    }
    float ma = fminf(fminf(a0, a1), a2);
    float mb = fminf(fminf(b0, b1), b2);
    if (i     < NREAL) atomicMin(&g_CM[b * NPAD + i],     __float_as_uint(ma));
    if (i + 1 < NREAL) atomicMin(&g_CM[b * NPAD + i + 1], __float_as_uint(mb));
}

// -------- final reduce: 1024 threads, float4, deep MLP ----------------------
__global__ void __launch_bounds__(1024) k_final(float* __restrict__ out) {
    __shared__ float sh[1024];
    const int tid = threadIdx.x;
    // 32768 u32 = 8192 uint4; thread tid takes 8 strided uint4 -> MLP 8
    float acc = 0.0f;
    const uint4* cm4 = (const uint4*)g_CM;
#pragma unroll
    for (int s = 0; s < 8; s++) {
        uint4 v = cm4[tid + s * 1024];
        int base = (tid + s * 1024) * 4;           // element index
        int ib = base & (NPAD - 1);
        // NREAL=8100: mask the padded tail of each image's 8192-slot block
        if (ib + 0 < NREAL) acc += __uint_as_float(v.x);
        if (ib + 1 < NREAL) acc += __uint_as_float(v.y);
        if (ib + 2 < NREAL) acc += __uint_as_float(v.z);
        if (ib + 3 < NREAL) acc += __uint_as_float(v.w);
    }
    sh[tid] = acc;
    __syncthreads();
    for (int s = 512; s > 0; s >>= 1) {
        if (tid < s) sh[tid] += sh[tid + s];
        __syncthreads();
    }
    if (tid == 0) out[0] = sh[0] * (1.0f / ((float)NIMG * (float)NREAL));
}

// -------- launch ------------------------------------------------------------
extern "C" void kernel_launch(void* const* d_in, const int* in_sizes, int n_in,
                              void* d_out, int out_size) {
    const float* x = (const float*)d_in[0];
    const float* y = (const float*)d_in[1];
    float* out = (float*)d_out;

    cudaFuncSetAttribute(k_pass0, cudaFuncAttributeMaxDynamicSharedMemorySize, SM_TOTAL);

    k_prep<<<NIMG * NPAD / 8, 256>>>(x, y);
    k_pass0<<<NWORKERS, 256, SM_TOTAL>>>();
    k_colmin<<<dim3(16, 18, NIMG), 256>>>();
    k_final<<<1, 1024>>>(out);
}

// round 17
// speedup vs baseline: 1.0095x; 1.0095x over previous
#include <cuda_runtime.h>
#include <cuda_fp16.h>
#include <stdint.h>

// Problem constants
#define NREAL 8100   // 90*90 valid patches per image
#define NPAD  8192   // padded patch count
#define DREAL 147    // 3*7*7
#define KSG   160    // K storage per patch row in global (bf16 elems; 320 B)
#define NIMG  4
#define ALPHA_F 0.05f
#define JCHUNK 64
#define TOTAL_ITEMS (NIMG * 64 * 128)   // (b, i-block, j-chunk) tuples = 32768
#define NWORKERS 296                    // 148 SMs x 2 CTAs

// -------- device scratch ----------------------------------------------------
// k storage is PAIR-PERMUTED within each 16-block (see k_prep); applied to
// BOTH X and Y so dot products and norms are unchanged.
__device__ uint16_t g_XP[NIMG * NPAD * KSG];   // bf16 bits
__device__ uint16_t g_YP[NIMG * NPAD * KSG];
__device__ float g_X2[NIMG * NPAD];
__device__ float g_Y2[NIMG * NPAD];
__device__ unsigned int g_RM[NIMG * NPAD];     // row mins (float bits)
__device__ unsigned int g_CM[NIMG * NPAD];     // col mins (float bits)
__device__ __half g_DH[(size_t)NIMG * NPAD * NPAD];  // [b][j][i] fp16 dist

__device__ __forceinline__ float finf() { return __int_as_float(0x7f800000); }

__device__ __forceinline__ uint16_t to_bf16(float v) {
    uint16_t u;
    asm("cvt.rn.bf16.f32 %0, %1;" : "=h"(u) : "f"(v));
    return u;
}

// bf16 warp MMA, K=16 (sm_80+; legal on plain sm_100 target)
#define MMA16(c0,c1,c2,c3,a0,a1,a2,a3,b0,b1) \
    asm volatile("mma.sync.aligned.m16n8k16.row.col.f32.bf16.bf16.f32 " \
        "{%0,%1,%2,%3}, {%4,%5,%6,%7}, {%8,%9}, {%0,%1,%2,%3};" \
        : "+f"(c0), "+f"(c1), "+f"(c2), "+f"(c3) \
        : "r"(a0), "r"(a1), "r"(a2), "r"(a3), "r"(b0), "r"(b1))

// SMEM (bytes): X 128x352 | Y 2 stages x 64x352 | fp16 staging 64x272 | RMS
#define SMB_X   0
#define SMB_Y   45056
#define SMB_ST  (45056 + 45056)
#define SMB_RMS (SMB_ST + 64 * 272)
#define SM_TOTAL (SMB_RMS + 1024)    // 108544 B -> 2 CTAs/SM

// -------- fused prep: extract bf16 (pair-permuted) + norms + min-init -------
__global__ void k_prep(const float* __restrict__ xsrc, const float* __restrict__ ysrc) {
    int row  = blockIdx.x * 8 + (threadIdx.x >> 5);
    int lane = threadIdx.x & 31;
    int b = row >> 13, n = row & (NPAD - 1);
    if (lane == 0) { g_RM[row] = 0x7f800000u; g_CM[row] = 0x7f800000u; }

    float sx = 0.0f, sy = 0.0f;
    if (lane < 20) {
        uint32_t px[4], py[4];
        const bool valid = (n < NREAL);
        const int oy = n / 90, ox = n - (n / 90) * 90;
        const float* xb = xsrc + b * 3 * 96 * 96;
        const float* yb = ysrc + b * 3 * 96 * 96;
#pragma unroll
        for (int e = 0; e < 8; e++) {
            int kq = lane * 8 + e;
            int s = kq & 15, p = s >> 1;
            int k = (kq & ~15) + (p & 1) * 8 + (p >> 1) * 2 + (s & 1);  // logical k
            uint32_t vx = 0, vy = 0;
            if (valid && k < DREAL) {
                int c = k / 49, rr = (k % 49) / 7, ss = k % 7;
                int off = ((c * 96) + oy + rr) * 96 + ox + ss;
                vx = to_bf16(xb[off]);
                vy = to_bf16(yb[off]);
                float fx = __uint_as_float(vx << 16); sx += fx * fx;
                float fy = __uint_as_float(vy << 16); sy += fy * fy;
            }
            if (e & 1) { px[e >> 1] |= vx << 16; py[e >> 1] |= vy << 16; }
            else       { px[e >> 1]  = vx;       py[e >> 1]  = vy; }
        }
        *(uint4*)((char*)g_XP + (size_t)row * 320 + lane * 16) =
            make_uint4(px[0], px[1], px[2], px[3]);
        *(uint4*)((char*)g_YP + (size_t)row * 320 + lane * 16) =
            make_uint4(py[0], py[1], py[2], py[3]);
    }
#pragma unroll
    for (int off = 16; off > 0; off >>= 1) {
        sx += __shfl_xor_sync(0xffffffffu, sx, off);
        sy += __shfl_xor_sync(0xffffffffu, sy, off);
    }
    if (lane == 0) { g_X2[row] = sx; g_Y2[row] = sy; }
}

// -------- pass 0: persistent balanced bf16 GEMM + row-min + fp16 dist -------
// Grid: exactly NWORKERS CTAs; CTA w owns items [w*T/296, (w+1)*T/296).
__global__ void __launch_bounds__(256, 2) k_pass0() {
    extern __shared__ char smem[];
    char* XS = smem + SMB_X;
    char* YS = smem + SMB_Y;
    char* ST = smem + SMB_ST;
    unsigned int* RMS = (unsigned int*)(smem + SMB_RMS);

    const int w = blockIdx.x;
    const int start = (int)(((long long)TOTAL_ITEMS * w) / NWORKERS);
    const int end   = (int)(((long long)TOTAL_ITEMS * (w + 1)) / NWORKERS);

    const int tid = threadIdx.x;
    const int lane = tid & 31;
    const int g = lane >> 2, t = lane & 3;
    const int wj = (tid >> 5) >> 2;
    const int wi = (tid >> 5) & 3;

    // per-thread Y-copy slot mapping (item-invariant)
    int sofs[5], gofs[5];
#pragma unroll
    for (int s = 0; s < 5; s++) {
        int v = tid + s * 256;
        int r = v / 20, q = v - r * 20;
        sofs[s] = r * 352 + q * 16;
        gofs[s] = r * 320 + q * 16;
    }

    // initial Y load for first item
    {
        int bi = start >> 7, jt = start & 127;
        const char* src = (const char*)g_YP
            + ((size_t)(bi >> 6) * NPAD + (size_t)jt * JCHUNK) * 320;
        char* Yst = YS + (start & 1) * 22528;
#pragma unroll
        for (int s = 0; s < 5; s++)
            *(float4*)(Yst + sofs[s]) = *(const float4*)(src + gofs[s]);
    }

    int cur_bi = -1;
    int b = 0, i0 = 0;
    float x2r[4][2];                       // pre-scaled by invD (+inf invalid)
    const float invD   = 1.0f / (float)DREAL;
    const float m2invD = -2.0f * invD;

    for (int item = start; item < end; item++) {
        const int bi = item >> 7;
        const int jt = item & 127;
        if (bi != cur_bi) {                // uniform branch
            cur_bi = bi;
            b  = bi >> 6;
            i0 = (bi & 63) * 128;
            __syncthreads();               // old XS reads fenced
            const float4* G4 = (const float4*)((const char*)g_XP
                                + ((size_t)b * NPAD + i0) * 320);
            float4* X4 = (float4*)XS;
            for (int v = tid; v < 128 * 20; v += 256) {
                int r = v / 20, q = v - r * 20;
                X4[r * 22 + q] = G4[r * 20 + q];
            }
#pragma unroll
            for (int nf = 0; nf < 4; nf++)
#pragma unroll
                for (int p = 0; p < 2; p++) {
                    int i = i0 + wi * 32 + nf * 8 + t * 2 + p;
                    x2r[nf][p] = (i < NREAL) ? g_X2[b * NPAD + i] * invD : finf();
                }
            __syncthreads();               // XS (and initial Y) visible
        }

        const char* Yu = YS + (item & 1) * 22528;

        // prefetch next item's Y into registers
        float4 pf[5];
        const bool havepf = (item + 1 < end);
        if (havepf) {
            int bin = (item + 1) >> 7, jtn = (item + 1) & 127;
            const char* Ygn = (const char*)g_YP
                + ((size_t)(bin >> 6) * NPAD + (size_t)jtn * JCHUNK) * 320;
#pragma unroll
            for (int s = 0; s < 5; s++) pf[s] = *(const float4*)(Ygn + gofs[s]);
        }

        // ---- 64x128 chunk GEMM: warp 32j x 32i, m16n8k16 bf16, 10 K-steps ---
        float c[2][4][4];
#pragma unroll
        for (int f = 0; f < 2; f++)
#pragma unroll
            for (int nf = 0; nf < 4; nf++)
#pragma unroll
                for (int k = 0; k < 4; k++) c[f][nf][k] = 0.0f;

#pragma unroll
        for (int ks = 0; ks < 10; ks++) {
            uint32_t a[2][4], bb[4][2];
            const int ko = ks * 32 + t * 8;
#pragma unroll
            for (int f = 0; f < 2; f++) {
                int row = wj * 32 + f * 16 + g;
                uint2 lo = *(const uint2*)(Yu + row * 352 + ko);
                uint2 hi = *(const uint2*)(Yu + (row + 8) * 352 + ko);
                a[f][0] = lo.x; a[f][2] = lo.y;
                a[f][1] = hi.x; a[f][3] = hi.y;
            }
#pragma unroll
            for (int nf = 0; nf < 4; nf++) {
                int col = wi * 32 + nf * 8 + g;
                uint2 bv = *(const uint2*)(XS + col * 352 + ko);
                bb[nf][0] = bv.x; bb[nf][1] = bv.y;
            }
#pragma unroll
            for (int f = 0; f < 2; f++)
#pragma unroll
                for (int nf = 0; nf < 4; nf++)
                    MMA16(c[f][nf][0], c[f][nf][1], c[f][nf][2], c[f][nf][3],
                          a[f][0], a[f][1], a[f][2], a[f][3], bb[nf][0], bb[nf][1]);
        }

        // commit prefetched Y to the other stage
        if (havepf) {
            char* Yn = YS + ((item + 1) & 1) * 22528;
#pragma unroll
            for (int s = 0; s < 5; s++) *(float4*)(Yn + sofs[s]) = pf[s];
        }

        // ---- epilogue: dist -> fp16 staging + row-min to RMS ---------------
        const int jbase = jt * JCHUNK;
#pragma unroll
        for (int f = 0; f < 2; f++)
#pragma unroll
            for (int h = 0; h < 2; h++) {
                int jl = wj * 32 + f * 16 + h * 8 + g;
                float y2s = g_Y2[b * NPAD + jbase + jl] * invD;
                float rm_ = finf();
                uint32_t* srow = (uint32_t*)(ST + jl * 272 + wi * 64 + t * 4);
#pragma unroll
                for (int nf = 0; nf < 4; nf++) {
                    float d0 = fmaxf(fmaf(c[f][nf][2*h],   m2invD, y2s + x2r[nf][0]), 0.0f);
                    float d1 = fmaxf(fmaf(c[f][nf][2*h+1], m2invD, y2s + x2r[nf][1]), 0.0f);
                    __half2 hp = __floats2half2_rn(d0, d1);
                    srow[nf * 4] = *(uint32_t*)&hp;
                    rm_ = fminf(rm_, fminf(d0, d1));
                }
                rm_ = fminf(rm_, __shfl_xor_sync(0xffffffffu, rm_, 1));
                rm_ = fminf(rm_, __shfl_xor_sync(0xffffffffu, rm_, 2));
                if (t == 0) RMS[wi * 64 + jl] = __float_as_uint(rm_);
            }
        __syncthreads();

        // coalesced STG of staging (64 rows x 256B) + row-min global reduce
        {
            char* gb = (char*)g_DH + (((size_t)b * NPAD + jbase) * NPAD + i0) * 2;
#pragma unroll
            for (int s2 = 0; s2 < 4; s2++) {
                int v = tid + s2 * 256;
                int r = v >> 4, q = v & 15;
                uint4 val = *(uint4*)(ST + r * 272 + q * 16);
                *(uint4*)(gb + (size_t)r * (NPAD * 2) + q * 16) = val;
            }
        }
        if (tid < 64) {
            unsigned int m = min(min(RMS[tid], RMS[64 + tid]),
                                 min(RMS[128 + tid], RMS[192 + tid]));
            int j = jbase + tid;
            if (j < NREAL) atomicMin(&g_RM[b * NPAD + j], m);
        }
        __syncthreads();
    }
}

// -------- pass 1: streaming column-min over fp16 dist (rinv fused) ----------
#define JSPLIT 450   // 18 * 450 = 8100
__global__ void __launch_bounds__(256) k_colmin() {
    __shared__ float rs[JSPLIT];
    const int b  = blockIdx.z;
    const int j0 = blockIdx.y * JSPLIT;
    const int i  = blockIdx.x * 512 + threadIdx.x * 2;

    for (int r = threadIdx.x; r < JSPLIT; r += 256) {
        float rm = __uint_as_float(g_RM[b * NPAD + j0 + r]);   // j0+r < NREAL
        rs[r] = 1.0f / (rm + ALPHA_F);
    }
    __syncthreads();

    const __half2* dp = (const __half2*)(g_DH + ((size_t)(b * NPAD + j0)) * NPAD + i);
    float a0 = finf(), a1 = finf(), a2 = finf();
    float b0 = finf(), b1 = finf(), b2 = finf();
    for (int j = 0; j < JSPLIT; j += 6) {   // 450 = 6*75
        __half2 u0 = dp[(size_t)(j + 0) * (NPAD / 2)];
        __half2 u1 = dp[(size_t)(j + 1) * (NPAD / 2)];
        __half2 u2 = dp[(size_t)(j + 2) * (NPAD / 2)];
        __half2 u3 = dp[(size_t)(j + 3) * (NPAD / 2)];
        __half2 u4 = dp[(size_t)(j + 4) * (NPAD / 2)];
        __half2 u5 = dp[(size_t)(j + 5) * (NPAD / 2)];
        float2 f0 = __half22float2(u0), f1 = __half22float2(u1);
        float2 f2 = __half22float2(u2), f3 = __half22float2(u3);
        float2 f4 = __half22float2(u4), f5 = __half22float2(u5);
        a0 = fminf(a0, f0.x * rs[j + 0]); b0 = fminf(b0, f0.y * rs[j + 0]);
        a1 = fminf(a1, f1.x * rs[j + 1]); b1 = fminf(b1, f1.y * rs[j + 1]);
        a2 = fminf(a2, f2.x * rs[j + 2]); b2 = fminf(b2, f2.y * rs[j + 2]);
        a0 = fminf(a0, f3.x * rs[j + 3]); b0 = fminf(b0, f3.y * rs[j + 3]);
        a1 = fminf(a1, f4.x * rs[j + 4]); b1 = fminf(b1, f4.y * rs[j + 4]);
        a2 = fminf(a2, f5.x * rs[j + 5]); b2 = fminf(b2, f5.y * rs[j + 5]);
    }
    float ma = fminf(fminf(a0, a1), a2);
    float mb = fminf(fminf(b0, b1), b2);
    if (i     < NREAL) atomicMin(&g_CM[b * NPAD + i],     __float_as_uint(ma));
    if (i + 1 < NREAL) atomicMin(&g_CM[b * NPAD + i + 1], __float_as_uint(mb));
}

// -------- final reduce: 1024 threads, float4, deep MLP ----------------------
__global__ void __launch_bounds__(1024) k_final(float* __restrict__ out) {
    __shared__ float sh[1024];
    const int tid = threadIdx.x;
    // 32768 u32 = 8192 uint4; thread tid takes 8 strided uint4 -> MLP 8
    float acc = 0.0f;
    const uint4* cm4 = (const uint4*)g_CM;
#pragma unroll
    for (int s = 0; s < 8; s++) {
        uint4 v = cm4[tid + s * 1024];
        int base = (tid + s * 1024) * 4;           // element index
        int ib = base & (NPAD - 1);
        // NREAL=8100: mask the padded tail of each image's 8192-slot block
        if (ib + 0 < NREAL) acc += __uint_as_float(v.x);
        if (ib + 1 < NREAL) acc += __uint_as_float(v.y);
        if (ib + 2 < NREAL) acc += __uint_as_float(v.z);
        if (ib + 3 < NREAL) acc += __uint_as_float(v.w);
    }
    sh[tid] = acc;
    __syncthreads();
    for (int s = 512; s > 0; s >>= 1) {
        if (tid < s) sh[tid] += sh[tid + s];
        __syncthreads();
    }
    if (tid == 0) out[0] = sh[0] * (1.0f / ((float)NIMG * (float)NREAL));
}

// -------- launch ------------------------------------------------------------
extern "C" void kernel_launch(void* const* d_in, const int* in_sizes, int n_in,
                              void* d_out, int out_size) {
    const float* x = (const float*)d_in[0];
    const float* y = (const float*)d_in[1];
    float* out = (float*)d_out;

    cudaFuncSetAttribute(k_pass0, cudaFuncAttributeMaxDynamicSharedMemorySize, SM_TOTAL);

    k_prep<<<NIMG * NPAD / 8, 256>>>(x, y);
    k_pass0<<<NWORKERS, 256, SM_TOTAL>>>();
    k_colmin<<<dim3(16, 18, NIMG), 256>>>();
    k_final<<<1, 1024>>>(out);
}